// round 1
// baseline (speedup 1.0000x reference)
#include <cuda_runtime.h>
#include <cstdint>

// Problem shapes (fixed for this registry entry)
#define BB   8
#define LC   16384
#define SSEQ 2048
#define HH   256
#define K2   512
#define MT   64          // rows per CTA
#define AS   516         // A smem stride (512 + 4 pad -> conflict-free frags)
#define WS   264         // W tile smem stride (256 + 8 pad -> conflict-free frags)
#define KT   32          // K tile
#define NKT  (K2 / KT)   // 16
#define NTH  256

__device__ __forceinline__ float to_tf32(float x) {
    uint32_t u;
    asm("cvt.rna.tf32.f32 %0, %1;" : "=r"(u) : "f"(x));
    return __uint_as_float(u);
}

__device__ __forceinline__ void mma_tf32(float d[4], const float a[4], const float b[2]) {
    asm volatile(
        "mma.sync.aligned.m16n8k8.row.col.f32.tf32.tf32.f32 "
        "{%0,%1,%2,%3}, {%4,%5,%6,%7}, {%8,%9}, {%0,%1,%2,%3};"
        : "+f"(d[0]), "+f"(d[1]), "+f"(d[2]), "+f"(d[3])
        : "r"(__float_as_uint(a[0])), "r"(__float_as_uint(a[1])),
          "r"(__float_as_uint(a[2])), "r"(__float_as_uint(a[3])),
          "r"(__float_as_uint(b[0])), "r"(__float_as_uint(b[1])));
}

__global__ __launch_bounds__(NTH, 1)
void syl_fused_kernel(const float* __restrict__ ce,
                      const void*  __restrict__ ta_raw,
                      const float* __restrict__ dh,
                      const float* __restrict__ W1, const float* __restrict__ b1,
                      const float* __restrict__ W2, const float* __restrict__ b2,
                      const float* __restrict__ gamma, const float* __restrict__ beta,
                      float* __restrict__ out)
{
    extern __shared__ float smem[];
    float* Asm = smem;                 // [MT][AS]  A = [char | tok/aligned] (tf32)
    float* Wt  = smem + MT * AS;       // [2][KT][WS] weight tiles (tf32)
    float* F   = Wt;                   // reused post-GEMM: [MT][WS] feats (fp32)
    __shared__ int s_is64;

    const int tid  = threadIdx.x;
    const int lane = tid & 31;
    const int wid  = tid >> 5;
    const int g    = lane >> 2;        // groupID
    const int tg   = lane & 3;         // thread-in-group
    const int wm   = wid & 1;          // warp M half (2 x 32 rows)
    const int wn   = wid >> 1;         // warp N quarter (4 x 64 cols)
    const int row0 = blockIdx.x * MT;

    // ---- dtype sniff for token_alignment (jax x64 off -> int32; on -> int64) ----
    if (tid == 0) {
        const int* t32 = (const int*)ta_raw;
        int ok = 1;
        #pragma unroll 1
        for (int k = 0; k < 64; k++) {
            int lo = t32[2 * k], hi = t32[2 * k + 1];
            if (!((hi == 0 && lo >= 0) || (hi == -1 && lo < 0))) { ok = 0; break; }
        }
        s_is64 = ok;
    }

    // ---- load char tile [MT x 256] -> Asm cols [0,256), cvt tf32 ----
    {
        const float4* ce4 = reinterpret_cast<const float4*>(ce + (size_t)row0 * HH);
        #pragma unroll
        for (int i = 0; i < (MT * HH / 4) / NTH; i++) {   // 16 float4 per thread
            int idx4 = tid + i * NTH;
            int r  = idx4 >> 6;
            int c4 = idx4 & 63;
            float4 v = ce4[idx4];
            float* dst = &Asm[r * AS + c4 * 4];
            dst[0] = to_tf32(v.x); dst[1] = to_tf32(v.y);
            dst[2] = to_tf32(v.z); dst[3] = to_tf32(v.w);
        }
    }
    __syncthreads();   // publish s_is64 (char stores don't conflict with gather region)
    const int is64 = s_is64;

    // ---- gather tok tile -> Asm cols [256,512), cvt tf32 ----
    {
        const long long* t64 = (const long long*)ta_raw;
        const int*       t32 = (const int*)ta_raw;
        #pragma unroll
        for (int rr = 0; rr < 8; rr++) {
            int r  = wid * 8 + rr;
            int gr = row0 + r;
            long long idx = is64 ? t64[gr] : (long long)t32[gr];
            float* dstrow = &Asm[r * AS + 256];
            if (idx < 0) {
                #pragma unroll
                for (int j = 0; j < 2; j++) {
                    int c4 = lane + j * 32;
                    float* dst = dstrow + c4 * 4;
                    dst[0] = 0.f; dst[1] = 0.f; dst[2] = 0.f; dst[3] = 0.f;
                }
            } else {
                int ii = (int)idx; if (ii > SSEQ - 1) ii = SSEQ - 1;
                int b = gr / LC;
                const float4* src = reinterpret_cast<const float4*>(dh + ((size_t)b * SSEQ + ii) * HH);
                #pragma unroll
                for (int j = 0; j < 2; j++) {
                    int c4 = lane + j * 32;
                    float4 v = src[c4];
                    float* dst = dstrow + c4 * 4;
                    dst[0] = to_tf32(v.x); dst[1] = to_tf32(v.y);
                    dst[2] = to_tf32(v.z); dst[3] = to_tf32(v.w);
                }
            }
        }
    }

    float acc[2][8][4];
    float4 wreg[8];

    // preload W1 tile 0 into registers
    {
        const float4* w4 = reinterpret_cast<const float4*>(W1);
        #pragma unroll
        for (int j = 0; j < 8; j++) wreg[j] = w4[tid + j * NTH];
    }

    const float* const Wg2[2] = { W1, W2 };

    #pragma unroll 1
    for (int gemm = 0; gemm < 2; gemm++) {
        #pragma unroll
        for (int mi = 0; mi < 2; mi++)
            #pragma unroll
            for (int ni = 0; ni < 8; ni++)
                #pragma unroll
                for (int c = 0; c < 4; c++) acc[mi][ni][c] = 0.f;

        #pragma unroll 1
        for (int kt = 0; kt < NKT; kt++) {
            float* wb = Wt + (kt & 1) * KT * WS;

            // commit staged W tile to smem (tf32)
            #pragma unroll
            for (int j = 0; j < 8; j++) {
                int idx4 = tid + j * NTH;
                int kk = idx4 >> 6;
                int c4 = idx4 & 63;
                float* dst = &wb[kk * WS + c4 * 4];
                dst[0] = to_tf32(wreg[j].x); dst[1] = to_tf32(wreg[j].y);
                dst[2] = to_tf32(wreg[j].z); dst[3] = to_tf32(wreg[j].w);
            }
            __syncthreads();

            // prefetch next W tile (overlaps with MMA below)
            {
                const float* nW = nullptr; int nkt = 0;
                if (kt < NKT - 1)      { nW = Wg2[gemm]; nkt = kt + 1; }
                else if (gemm == 0)    { nW = W2;        nkt = 0; }
                if (nW) {
                    const float4* w4 = reinterpret_cast<const float4*>(nW + nkt * KT * HH);
                    #pragma unroll
                    for (int j = 0; j < 8; j++) wreg[j] = w4[tid + j * NTH];
                }
            }

            // 4 k-steps of m16n8k8 tf32 mma
            #pragma unroll
            for (int ks = 0; ks < 4; ks++) {
                int kc = kt * KT + ks * 8;
                float a[2][4];
                #pragma unroll
                for (int mi = 0; mi < 2; mi++) {
                    int rb = wm * 32 + mi * 16;
                    const float* ap  = &Asm[(rb + g) * AS + kc + tg];
                    const float* ap2 = &Asm[(rb + 8 + g) * AS + kc + tg];
                    a[mi][0] = ap[0];  a[mi][2] = ap[4];
                    a[mi][1] = ap2[0]; a[mi][3] = ap2[4];
                }
                float bf[8][2];
                #pragma unroll
                for (int ni = 0; ni < 8; ni++) {
                    int bc = wn * 64 + ni * 8 + g;
                    bf[ni][0] = wb[(ks * 8 + tg)     * WS + bc];
                    bf[ni][1] = wb[(ks * 8 + tg + 4) * WS + bc];
                }
                #pragma unroll
                for (int mi = 0; mi < 2; mi++)
                    #pragma unroll
                    for (int ni = 0; ni < 8; ni++)
                        mma_tf32(acc[mi][ni], a[mi], bf[ni]);
            }
        }
        __syncthreads();   // all mma reads of Asm/Wt complete

        if (gemm == 0) {
            // epilogue 1: aligned = acc + b1 -> Asm cols [256,512) (tf32)
            #pragma unroll
            for (int mi = 0; mi < 2; mi++)
                #pragma unroll
                for (int ni = 0; ni < 8; ni++)
                    #pragma unroll
                    for (int c = 0; c < 4; c++) {
                        int row = wm * 32 + mi * 16 + g + ((c >> 1) << 3);
                        int col = wn * 64 + ni * 8 + tg * 2 + (c & 1);
                        Asm[row * AS + 256 + col] = to_tf32(acc[mi][ni][c] + b1[col]);
                    }
            __syncthreads();
        }
    }

    // epilogue 2: feats = acc + b2 -> F (fp32, reuses Wt region)
    #pragma unroll
    for (int mi = 0; mi < 2; mi++)
        #pragma unroll
        for (int ni = 0; ni < 8; ni++)
            #pragma unroll
            for (int c = 0; c < 4; c++) {
                int row = wm * 32 + mi * 16 + g + ((c >> 1) << 3);
                int col = wn * 64 + ni * 8 + tg * 2 + (c & 1);
                F[row * WS + col] = acc[mi][ni][c] + b2[col];
            }
    __syncthreads();

    // LayerNorm + exact GELU + residual, one warp per row (8 rows per warp)
    #pragma unroll
    for (int rr = 0; rr < 8; rr++) {
        int r = wid * 8 + rr;
        float x[8];
        #pragma unroll
        for (int j = 0; j < 8; j++) x[j] = F[r * WS + lane + j * 32];
        float s = 0.f, q = 0.f;
        #pragma unroll
        for (int j = 0; j < 8; j++) { s += x[j]; q += x[j] * x[j]; }
        #pragma unroll
        for (int o = 16; o; o >>= 1) {
            s += __shfl_xor_sync(0xffffffffu, s, o);
            q += __shfl_xor_sync(0xffffffffu, q, o);
        }
        float mu  = s * (1.0f / HH);
        float var = q * (1.0f / HH) - mu * mu;
        float rs  = rsqrtf(var + 1e-5f);
        int gbase = (row0 + r) * HH;
        #pragma unroll
        for (int j = 0; j < 8; j++) {
            int c = lane + j * 32;
            float v = (x[j] - mu) * rs * gamma[c] + beta[c];
            float gel = 0.5f * v * (1.0f + erff(v * 0.70710678118654752440f));
            out[gbase + c] = ce[gbase + c] + gel;
        }
    }
}

extern "C" void kernel_launch(void* const* d_in, const int* in_sizes, int n_in,
                              void* d_out, int out_size)
{
    const float* ce    = (const float*)d_in[0];
    const void*  ta    = d_in[1];
    const float* dh    = (const float*)d_in[2];
    const float* W1    = (const float*)d_in[3];
    const float* b1    = (const float*)d_in[4];
    const float* W2    = (const float*)d_in[5];
    const float* b2    = (const float*)d_in[6];
    const float* gamma = (const float*)d_in[7];
    const float* beta  = (const float*)d_in[8];
    float* out = (float*)d_out;

    int M = in_sizes[1];          // B*Lc = 131072
    int grid = M / MT;            // 2048 CTAs
    size_t shmem = (size_t)(MT * AS + 2 * KT * WS) * sizeof(float);  // 199,680 B

    cudaFuncSetAttribute(syl_fused_kernel,
                         cudaFuncAttributeMaxDynamicSharedMemorySize, (int)shmem);
    syl_fused_kernel<<<grid, NTH, shmem>>>(ce, ta, dh, W1, b1, W2, b2, gamma, beta, out);
}